// round 5
// baseline (speedup 1.0000x reference)
#include <cuda_runtime.h>
#include <cuda_fp16.h>

#define NN 50000
#define EE 800000
#define HH 64
#define PP 20
#define GG 500
#define NB 391           // (NN+127)/128, 128-row gemm tiles
#define AGB 6250         // NN/8 warps-per-block aggr blocks per part

// ---------------- device scratch ----------
__device__ float g_pe[NN * HH];
__device__ float g_h[NN * HH];
__device__ __align__(16) __half2 g_tmpH[NN * (HH / 2)];   // fp16 messages, 128B/row
__device__ __align__(16) __half2 g_tmpP[NN * (HH / 2)];
__device__ float g_dinv[NN];
__device__ int   g_deg[NN];
__device__ int   g_offs[NN + 1];
__device__ int   g_cursor[NN];
__device__ int   g_csr[EE];
__device__ int   g_bsum[64];
__device__ float g_bnsum[HH], g_bnsum2[HH];

// ---------------- packed f32x2 helpers ----------
__device__ __forceinline__ unsigned long long pack2(float x, float y) {
    unsigned long long r;
    asm("mov.b64 %0, {%1, %2};" : "=l"(r) : "f"(x), "f"(y));
    return r;
}
__device__ __forceinline__ void unpack2(unsigned long long v, float& x, float& y) {
    asm("mov.b64 {%0, %1}, %2;" : "=f"(x), "=f"(y) : "l"(v));
}
__device__ __forceinline__ void ffma2(unsigned long long& d, unsigned long long a,
                                      unsigned long long b) {
    asm("fma.rn.f32x2 %0, %1, %2, %0;" : "+l"(d) : "l"(a), "l"(b));
}

// ---------------- CSR build ------------------------------------------------
__global__ void k_zero() {
    int i = blockIdx.x * blockDim.x + threadIdx.x;
    if (i < NN) g_deg[i] = 0;
    if (i < HH) { g_bnsum[i] = 0.f; g_bnsum2[i] = 0.f; }
}

__global__ void k_deg(const int* __restrict__ dst) {
    int i = blockIdx.x * blockDim.x + threadIdx.x;
    if (i < EE) atomicAdd(&g_deg[dst[i]], 1);
}

__global__ void k_scan_part() {
    __shared__ int sh[1024];
    int t = threadIdx.x;
    int i = blockIdx.x * 1024 + t;
    sh[t] = (i < NN) ? g_deg[i] : 0;
    __syncthreads();
    for (int s = 512; s > 0; s >>= 1) {
        if (t < s) sh[t] += sh[t + s];
        __syncthreads();
    }
    if (t == 0) g_bsum[blockIdx.x] = sh[0];
}

__global__ void k_scan_final() {
    __shared__ int bs[64];
    __shared__ int sh[1024];
    int t = threadIdx.x;
    if (t < 64) bs[t] = (t < 49) ? g_bsum[t] : 0;
    __syncthreads();
    if (t == 0) {
        int run = 0;
        for (int i = 0; i < 49; i++) { int v = bs[i]; bs[i] = run; run += v; }
    }
    int i = blockIdx.x * 1024 + t;
    int v = (i < NN) ? g_deg[i] : 0;
    sh[t] = v;
    __syncthreads();
    for (int d = 1; d < 1024; d <<= 1) {
        int x = (t >= d) ? sh[t - d] : 0;
        __syncthreads();
        sh[t] += x;
        __syncthreads();
    }
    int excl = sh[t] - v + bs[blockIdx.x];
    if (i < NN) {
        g_offs[i] = excl;
        g_cursor[i] = excl;
        g_dinv[i] = rsqrtf((float)v + 1.0f);
        if (i == NN - 1) g_offs[NN] = excl + v;
    }
}

__global__ void k_scatter(const int* __restrict__ src, const int* __restrict__ dst) {
    int i = blockIdx.x * blockDim.x + threadIdx.x;
    if (i >= EE) return;
    int d = dst[i];
    int pos = atomicAdd(&g_cursor[d], 1);
    g_csr[pos] = src[i];
}

// ---------------- rw GEMM: pe = RWPE @ W_rw + b_rw (K=20, fp32 out) --------
__global__ void k_gemm_rw(const float* __restrict__ A, const float* __restrict__ W,
                          const float* __restrict__ bias, float* __restrict__ out) {
    __shared__ __align__(16) float in_s[64][PP];
    __shared__ __align__(16) float wt_s[PP][64];
    int tid = threadIdx.x;
    int row0 = blockIdx.x * 64;
    {
        const float4* W4 = (const float4*)W;
        float4* ws4 = (float4*)&wt_s[0][0];
        for (int i = tid; i < PP * 16; i += 256) ws4[i] = W4[i];
    }
    {
        const float4* A4 = (const float4*)A;
        for (int i = tid; i < 64 * 5; i += 256) {
            int r = i / 5, c = i % 5;
            int row = row0 + r;
            float4 v = make_float4(0.f, 0.f, 0.f, 0.f);
            if (row < NN) v = A4[row * 5 + c];
            *(((float4*)in_s[r]) + c) = v;
        }
    }
    __syncthreads();
    int tx = tid & 15, ty = tid >> 4;
    float acc[4][4];
#pragma unroll
    for (int i = 0; i < 4; i++)
#pragma unroll
        for (int j = 0; j < 4; j++) acc[i][j] = 0.f;
#pragma unroll
    for (int k = 0; k < PP; k += 4) {
        float4 a[4], b[4];
#pragma unroll
        for (int i = 0; i < 4; i++) a[i] = *(const float4*)&in_s[ty * 4 + i][k];
#pragma unroll
        for (int kk = 0; kk < 4; kk++) b[kk] = *(const float4*)&wt_s[k + kk][tx * 4];
#pragma unroll
        for (int i = 0; i < 4; i++) {
            acc[i][0] += a[i].x * b[0].x + a[i].y * b[1].x + a[i].z * b[2].x + a[i].w * b[3].x;
            acc[i][1] += a[i].x * b[0].y + a[i].y * b[1].y + a[i].z * b[2].y + a[i].w * b[3].y;
            acc[i][2] += a[i].x * b[0].z + a[i].y * b[1].z + a[i].z * b[2].z + a[i].w * b[3].z;
            acc[i][3] += a[i].x * b[0].w + a[i].y * b[1].w + a[i].z * b[2].w + a[i].w * b[3].w;
        }
    }
#pragma unroll
    for (int i = 0; i < 4; i++) {
        int row = row0 + ty * 4 + i;
        if (row >= NN) continue;
        float4 o;
        o.x = acc[i][0] + bias[tx * 4 + 0];
        o.y = acc[i][1] + bias[tx * 4 + 1];
        o.z = acc[i][2] + bias[tx * 4 + 2];
        o.w = acc[i][3] + bias[tx * 4 + 3];
        *(float4*)&out[row * 64 + tx * 4] = o;
    }
}

// ---------------- dual 64x64 GEMM, packed f32x2, fp16 out ------------------
// part0: (A0 + A20) @ W0 * dinv -> outH ;  part1: A1 @ W1 * dinv -> outP
__global__ void __launch_bounds__(256) k_dualgemm(
        const float* __restrict__ A0, const float* __restrict__ A20,
        const float* __restrict__ W0, __half2* __restrict__ outH,
        const float* __restrict__ A1, const float* __restrict__ W1,
        __half2* __restrict__ outP) {
    __shared__ __align__(16) float in_s[128][64];
    __shared__ __align__(16) float wt_s[64][64];
    int tid = threadIdx.x;
    int part = (blockIdx.x >= NB) ? 1 : 0;
    int bx = blockIdx.x - part * NB;
    int row0 = bx * 128;

    const float* A  = part ? A1 : A0;
    const float* A2 = part ? nullptr : A20;
    const float* W  = part ? W1 : W0;
    __half2* out    = part ? outP : outH;

    // stage W (native k-major layout)
    {
        const float4* W4 = (const float4*)W;
        float4* ws4 = (float4*)&wt_s[0][0];
        for (int i = tid; i < 1024; i += 256) ws4[i] = W4[i];
    }
    // stage A (+A2 for part0)
    {
        const float4* A4  = (const float4*)A;
        const float4* A24 = (const float4*)A2;
        for (int i = tid; i < 128 * 16; i += 256) {
            int r = i >> 4, c = i & 15;
            int row = row0 + r;
            float4 v = make_float4(0.f, 0.f, 0.f, 0.f);
            if (row < NN) {
                v = A4[row * 16 + c];
                if (!part) {
                    float4 w = A24[row * 16 + c];
                    v.x += w.x; v.y += w.y; v.z += w.z; v.w += w.w;
                }
            }
            *(((float4*)in_s[r]) + c) = v;
        }
    }
    __syncthreads();

    int tx = tid & 7;          // 8 -> 8 cols each
    int ty = tid >> 3;         // 32 -> 4 rows each
    int r0 = ty * 4, c0 = tx * 8;

    unsigned long long acc[4][4];
#pragma unroll
    for (int i = 0; i < 4; i++)
#pragma unroll
        for (int p = 0; p < 4; p++) acc[i][p] = pack2(0.f, 0.f);

#pragma unroll
    for (int k = 0; k < 64; k += 4) {
        float4 a[4];
#pragma unroll
        for (int i = 0; i < 4; i++) a[i] = *(const float4*)&in_s[r0 + i][k];
        ulonglong2 b0[4], b1[4];
#pragma unroll
        for (int kk = 0; kk < 4; kk++) {
            b0[kk] = *(const ulonglong2*)&wt_s[k + kk][c0];
            b1[kk] = *(const ulonglong2*)&wt_s[k + kk][c0 + 4];
        }
#pragma unroll
        for (int i = 0; i < 4; i++) {
            float av[4] = {a[i].x, a[i].y, a[i].z, a[i].w};
#pragma unroll
            for (int kk = 0; kk < 4; kk++) {
                unsigned long long ap = pack2(av[kk], av[kk]);
                ffma2(acc[i][0], ap, b0[kk].x);
                ffma2(acc[i][1], ap, b0[kk].y);
                ffma2(acc[i][2], ap, b1[kk].x);
                ffma2(acc[i][3], ap, b1[kk].y);
            }
        }
    }

#pragma unroll
    for (int i = 0; i < 4; i++) {
        int row = row0 + r0 + i;
        if (row >= NN) continue;
        float s = g_dinv[row];
        uint4 pk;
        float x0, x1;
        unpack2(acc[i][0], x0, x1);
        __half2 h0 = __floats2half2_rn(x0 * s, x1 * s);
        unpack2(acc[i][1], x0, x1);
        __half2 h1 = __floats2half2_rn(x0 * s, x1 * s);
        unpack2(acc[i][2], x0, x1);
        __half2 h2 = __floats2half2_rn(x0 * s, x1 * s);
        unpack2(acc[i][3], x0, x1);
        __half2 h3 = __floats2half2_rn(x0 * s, x1 * s);
        pk.x = (*(unsigned int*)&h0);
        pk.y = (*(unsigned int*)&h1);
        pk.z = (*(unsigned int*)&h2);
        pk.w = (*(unsigned int*)&h3);
        ((uint4*)out)[row * 8 + tx] = pk;   // 8 uint4 per 128B row
    }
}

// ---------------- dual sparse aggregation (warp per node) ------------------
// part0: h[d]  = relu0?( (sum tmpH[nbr] + tmpH[d]) * dinv + bc )
// part1: pe[d] = relu (  (sum tmpP[nbr] + tmpP[d]) * dinv + bp )
__global__ void k_dualaggr(const __half2* __restrict__ tH, const float* __restrict__ bc,
                           float* __restrict__ h, int relu0,
                           const __half2* __restrict__ tP, const float* __restrict__ bp,
                           float* __restrict__ pe) {
    int gw = (blockIdx.x * blockDim.x + threadIdx.x) >> 5;
    int lane = threadIdx.x & 31;
    const __half2* t2;
    const float* bias;
    float* out;
    int relu, wid;
    if (gw < NN) {
        t2 = tH; bias = bc; out = h; relu = relu0; wid = gw;
    } else {
        wid = gw - NN;
        if (wid >= NN) return;
        t2 = tP; bias = bp; out = pe; relu = 1;
    }
    int beg = g_offs[wid], end = g_offs[wid + 1];
    float2 acc = __half22float2(t2[wid * 32 + lane]);  // self term (already *dinv)
    int e = beg;
    for (; e + 4 <= end; e += 4) {
        int s0 = g_csr[e], s1 = g_csr[e + 1], s2 = g_csr[e + 2], s3 = g_csr[e + 3];
        float2 v0 = __half22float2(t2[s0 * 32 + lane]);
        float2 v1 = __half22float2(t2[s1 * 32 + lane]);
        float2 v2 = __half22float2(t2[s2 * 32 + lane]);
        float2 v3 = __half22float2(t2[s3 * 32 + lane]);
        acc.x += (v0.x + v1.x) + (v2.x + v3.x);
        acc.y += (v0.y + v1.y) + (v2.y + v3.y);
    }
    for (; e < end; e++) {
        int s = g_csr[e];
        float2 v = __half22float2(t2[s * 32 + lane]);
        acc.x += v.x; acc.y += v.y;
    }
    float d = g_dinv[wid];
    float2 bv = ((const float2*)bias)[lane];
    float ox = acc.x * d + bv.x;
    float oy = acc.y * d + bv.y;
    if (relu) { ox = fmaxf(ox, 0.f); oy = fmaxf(oy, 0.f); }
    ((float2*)out)[wid * 32 + lane] = make_float2(ox, oy);
}

// ---------------- BatchNorm stats + fused norm/relu/pool -------------------
__global__ void k_bn_stats(const float* __restrict__ h) {
    int t = threadIdx.x;
    int col = t & 63, sub = t >> 6;
    float s = 0.f, s2 = 0.f;
    for (int r = blockIdx.x * 4 + sub; r < NN; r += gridDim.x * 4) {
        float v = h[r * 64 + col];
        s += v; s2 += v * v;
    }
    __shared__ float sh[4][64], sh2[4][64];
    sh[sub][col] = s; sh2[sub][col] = s2;
    __syncthreads();
    if (sub == 0) {
        float ts = sh[0][col] + sh[1][col] + sh[2][col] + sh[3][col];
        float t2 = sh2[0][col] + sh2[1][col] + sh2[2][col] + sh2[3][col];
        atomicAdd(&g_bnsum[col], ts);
        atomicAdd(&g_bnsum2[col], t2);
    }
}

__global__ void k_pool(const float* __restrict__ h, const int* __restrict__ ptr,
                       const float* __restrict__ gamma, const float* __restrict__ beta,
                       float* __restrict__ out) {
    __shared__ float sscale[64], sshift[64];
    int t = threadIdx.x;
    if (t < 64) {
        float mu = g_bnsum[t] / (float)NN;
        float var = g_bnsum2[t] / (float)NN - mu * mu;
        float r = rsqrtf(var + 1e-5f);
        float sc = r * gamma[t];
        sscale[t] = sc;
        sshift[t] = beta[t] - mu * sc;
    }
    __syncthreads();
    int g = blockIdx.x;
    int beg = ptr[g], end = ptr[g + 1];
    int col = t & 63, sub = t >> 6;
    float acc = 0.f;
    for (int r = beg + sub; r < end; r += 4) {
        float v = h[r * 64 + col] * sscale[col] + sshift[col];
        acc += fmaxf(v, 0.f);
    }
    __shared__ float sh[4][64];
    sh[sub][col] = acc;
    __syncthreads();
    if (sub == 0) {
        float s = sh[0][col] + sh[1][col] + sh[2][col] + sh[3][col];
        out[g * 64 + col] = s / (float)(end - beg);
    }
}

// ---------------- launch ----------------------------------------------------
extern "C" void kernel_launch(void* const* d_in, const int* in_sizes, int n_in,
                              void* d_out, int out_size) {
    const float* x     = (const float*)d_in[0];
    const float* rwpe  = (const float*)d_in[1];
    const float* W_rw  = (const float*)d_in[2];
    const float* b_rw  = (const float*)d_in[3];
    const float *Wc[5], *bc[5], *Wp[5], *bp[5];
    for (int i = 0; i < 5; i++) {
        Wc[i] = (const float*)d_in[4 + 4 * i];
        bc[i] = (const float*)d_in[5 + 4 * i];
        Wp[i] = (const float*)d_in[6 + 4 * i];
        bp[i] = (const float*)d_in[7 + 4 * i];
    }
    const float* gamma = (const float*)d_in[24];
    const float* beta  = (const float*)d_in[25];
    const int*   ei    = (const int*)d_in[26];
    const int*   ptr   = (const int*)d_in[27];
    float*       out   = (float*)d_out;
    const int* src = ei;
    const int* dst = ei + EE;

    float *pe, *h;
    __half2 *tH, *tP;
    cudaGetSymbolAddress((void**)&pe, g_pe);
    cudaGetSymbolAddress((void**)&h, g_h);
    cudaGetSymbolAddress((void**)&tH, g_tmpH);
    cudaGetSymbolAddress((void**)&tP, g_tmpP);

    // CSR build
    k_zero<<<(NN + 255) / 256, 256>>>();
    k_deg<<<(EE + 255) / 256, 256>>>(dst);
    k_scan_part<<<49, 1024>>>();
    k_scan_final<<<49, 1024>>>();
    k_scatter<<<(EE + 255) / 256, 256>>>(src, dst);

    // pe0 = RWPE @ W_rw + b_rw
    k_gemm_rw<<<(NN + 63) / 64, 256>>>(rwpe, W_rw, b_rw, pe);

    // layer 1: tmpH = (x+pe0)Wc1*dinv ; tmpP = pe0*Wp1*dinv
    k_dualgemm<<<2 * NB, 256>>>(x, pe, Wc[0], tH, pe, Wp[0], tP);
    // h = relu(agg(tmpH)+bc1) ; pe = relu(agg(tmpP)+bp1)
    k_dualaggr<<<2 * AGB, 256>>>(tH, bc[0], h, 1, tP, bp[0], pe);

    // layers 2..4: dual; layer 5: h-branch only, no relu
    for (int k = 1; k <= 3; k++) {
        k_dualgemm<<<2 * NB, 256>>>(h, pe, Wc[k], tH, pe, Wp[k], tP);
        k_dualaggr<<<2 * AGB, 256>>>(tH, bc[k], h, 1, tP, bp[k], pe);
    }
    k_dualgemm<<<NB, 256>>>(h, pe, Wc[4], tH, pe, Wp[4], tP);   // part0 only
    k_dualaggr<<<AGB, 256>>>(tH, bc[4], h, 0, tP, bp[4], pe);   // part0 only, no relu

    // BatchNorm (training stats) + relu + mean-pool per graph
    k_bn_stats<<<128, 256>>>(h);
    k_pool<<<GG, 256>>>(h, ptr, gamma, beta, out);
}

// round 6
// speedup vs baseline: 1.3814x; 1.3814x over previous
#include <cuda_runtime.h>
#include <cuda_fp16.h>

#define NN 50000
#define EE 800000
#define HH 64
#define PP 20
#define GG 500
#define NB 391           // (NN+127)/128, 128-row gemm tiles
#define AGB 6250         // NN/8 warps-per-block aggr blocks per part

// ---------------- device scratch ----------
__device__ float g_pe[NN * HH];
__device__ float g_h[NN * HH];
__device__ __align__(16) __half2 g_tmpH[NN * (HH / 2)];   // fp16 messages, 128B/row
__device__ __align__(16) __half2 g_tmpP[NN * (HH / 2)];
__device__ float g_dinv[NN];
__device__ int   g_deg[NN];
__device__ int   g_offs[NN + 1];
__device__ int   g_cursor[NN];
__device__ int   g_csr[EE];
__device__ int   g_bsum[64];
__device__ float g_bnsum[HH], g_bnsum2[HH];

// ---------------- mma/ldmatrix helpers ----------
__device__ __forceinline__ void ldsm_x4(unsigned& d0, unsigned& d1, unsigned& d2, unsigned& d3,
                                        unsigned addr) {
    asm volatile("ldmatrix.sync.aligned.m8n8.x4.shared.b16 {%0,%1,%2,%3}, [%4];"
                 : "=r"(d0), "=r"(d1), "=r"(d2), "=r"(d3) : "r"(addr));
}
__device__ __forceinline__ void ldsm_x4_t(unsigned& d0, unsigned& d1, unsigned& d2, unsigned& d3,
                                          unsigned addr) {
    asm volatile("ldmatrix.sync.aligned.m8n8.x4.trans.shared.b16 {%0,%1,%2,%3}, [%4];"
                 : "=r"(d0), "=r"(d1), "=r"(d2), "=r"(d3) : "r"(addr));
}
__device__ __forceinline__ void mma16816(float* c, unsigned a0, unsigned a1, unsigned a2,
                                         unsigned a3, unsigned b0, unsigned b1) {
    asm volatile(
        "mma.sync.aligned.m16n8k16.row.col.f32.f16.f16.f32 "
        "{%0,%1,%2,%3}, {%4,%5,%6,%7}, {%8,%9}, {%0,%1,%2,%3};"
        : "+f"(c[0]), "+f"(c[1]), "+f"(c[2]), "+f"(c[3])
        : "r"(a0), "r"(a1), "r"(a2), "r"(a3), "r"(b0), "r"(b1));
}

// ---------------- CSR build ------------------------------------------------
__global__ void k_zero() {
    int i = blockIdx.x * blockDim.x + threadIdx.x;
    if (i < NN) g_deg[i] = 0;
    if (i < HH) { g_bnsum[i] = 0.f; g_bnsum2[i] = 0.f; }
}

__global__ void k_deg(const int* __restrict__ dst) {
    int i = blockIdx.x * blockDim.x + threadIdx.x;
    if (i < EE) atomicAdd(&g_deg[dst[i]], 1);
}

__global__ void k_scan_part() {
    __shared__ int sh[1024];
    int t = threadIdx.x;
    int i = blockIdx.x * 1024 + t;
    sh[t] = (i < NN) ? g_deg[i] : 0;
    __syncthreads();
    for (int s = 512; s > 0; s >>= 1) {
        if (t < s) sh[t] += sh[t + s];
        __syncthreads();
    }
    if (t == 0) g_bsum[blockIdx.x] = sh[0];
}

__global__ void k_scan_final() {
    __shared__ int bs[64];
    __shared__ int sh[1024];
    int t = threadIdx.x;
    if (t < 64) bs[t] = (t < 49) ? g_bsum[t] : 0;
    __syncthreads();
    if (t == 0) {
        int run = 0;
        for (int i = 0; i < 49; i++) { int v = bs[i]; bs[i] = run; run += v; }
    }
    int i = blockIdx.x * 1024 + t;
    int v = (i < NN) ? g_deg[i] : 0;
    sh[t] = v;
    __syncthreads();
    for (int d = 1; d < 1024; d <<= 1) {
        int x = (t >= d) ? sh[t - d] : 0;
        __syncthreads();
        sh[t] += x;
        __syncthreads();
    }
    int excl = sh[t] - v + bs[blockIdx.x];
    if (i < NN) {
        g_offs[i] = excl;
        g_cursor[i] = excl;
        g_dinv[i] = rsqrtf((float)v + 1.0f);
        if (i == NN - 1) g_offs[NN] = excl + v;
    }
}

__global__ void k_scatter(const int* __restrict__ src, const int* __restrict__ dst) {
    int i = blockIdx.x * blockDim.x + threadIdx.x;
    if (i >= EE) return;
    int d = dst[i];
    int pos = atomicAdd(&g_cursor[d], 1);
    g_csr[pos] = src[i];
}

// ---------------- rw GEMM: pe = RWPE @ W_rw + b_rw (K=20, fp32, scalar) ----
__global__ void k_gemm_rw(const float* __restrict__ A, const float* __restrict__ W,
                          const float* __restrict__ bias, float* __restrict__ out) {
    __shared__ __align__(16) float in_s[64][PP];
    __shared__ __align__(16) float wt_s[PP][64];
    int tid = threadIdx.x;
    int row0 = blockIdx.x * 64;
    {
        const float4* W4 = (const float4*)W;
        float4* ws4 = (float4*)&wt_s[0][0];
        for (int i = tid; i < PP * 16; i += 256) ws4[i] = W4[i];
    }
    {
        const float4* A4 = (const float4*)A;
        for (int i = tid; i < 64 * 5; i += 256) {
            int r = i / 5, c = i % 5;
            int row = row0 + r;
            float4 v = make_float4(0.f, 0.f, 0.f, 0.f);
            if (row < NN) v = A4[row * 5 + c];
            *(((float4*)in_s[r]) + c) = v;
        }
    }
    __syncthreads();
    int tx = tid & 15, ty = tid >> 4;
    float acc[4][4];
#pragma unroll
    for (int i = 0; i < 4; i++)
#pragma unroll
        for (int j = 0; j < 4; j++) acc[i][j] = 0.f;
#pragma unroll
    for (int k = 0; k < PP; k += 4) {
        float4 a[4], b[4];
#pragma unroll
        for (int i = 0; i < 4; i++) a[i] = *(const float4*)&in_s[ty * 4 + i][k];
#pragma unroll
        for (int kk = 0; kk < 4; kk++) b[kk] = *(const float4*)&wt_s[k + kk][tx * 4];
#pragma unroll
        for (int i = 0; i < 4; i++) {
            acc[i][0] += a[i].x * b[0].x + a[i].y * b[1].x + a[i].z * b[2].x + a[i].w * b[3].x;
            acc[i][1] += a[i].x * b[0].y + a[i].y * b[1].y + a[i].z * b[2].y + a[i].w * b[3].y;
            acc[i][2] += a[i].x * b[0].z + a[i].y * b[1].z + a[i].z * b[2].z + a[i].w * b[3].z;
            acc[i][3] += a[i].x * b[0].w + a[i].y * b[1].w + a[i].z * b[2].w + a[i].w * b[3].w;
        }
    }
#pragma unroll
    for (int i = 0; i < 4; i++) {
        int row = row0 + ty * 4 + i;
        if (row >= NN) continue;
        float4 o;
        o.x = acc[i][0] + bias[tx * 4 + 0];
        o.y = acc[i][1] + bias[tx * 4 + 1];
        o.z = acc[i][2] + bias[tx * 4 + 2];
        o.w = acc[i][3] + bias[tx * 4 + 3];
        *(float4*)&out[row * 64 + tx * 4] = o;
    }
}

// ---------------- dual 128x64x64 HMMA GEMM, fp16 in/out, fp32 acc ----------
// part0: (A0 + A20) @ W0 * dinv -> outH ;  part1: A1 @ W1 * dinv -> outP
// smem: fp16 tiles padded to 72 halves/row (144B stride -> conflict-free ldmatrix)
__global__ void __launch_bounds__(256) k_dualgemm(
        const float* __restrict__ A0, const float* __restrict__ A20,
        const float* __restrict__ W0, __half2* __restrict__ outH,
        const float* __restrict__ A1, const float* __restrict__ W1,
        __half2* __restrict__ outP) {
    __shared__ __align__(16) __half a_s[128][72];
    __shared__ __align__(16) __half b_s[64][72];
    int tid = threadIdx.x;
    int part = (blockIdx.x >= NB) ? 1 : 0;
    int bx = blockIdx.x - part * NB;
    int row0 = bx * 128;

    const float* A  = part ? A1 : A0;
    const float* A2 = part ? nullptr : A20;
    const float* W  = part ? W1 : W0;
    __half2* out    = part ? outP : outH;

    // stage W fp32 -> fp16  (k-major, [64][64])
    {
        const float4* W4 = (const float4*)W;
        for (int i = tid; i < 64 * 16; i += 256) {
            int k = i >> 4, c4 = i & 15;
            float4 v = W4[i];
            *(__half2*)&b_s[k][c4 * 4]     = __floats2half2_rn(v.x, v.y);
            *(__half2*)&b_s[k][c4 * 4 + 2] = __floats2half2_rn(v.z, v.w);
        }
    }
    // stage A (+A2) fp32 -> fp16
    {
        const float4* A4  = (const float4*)A;
        const float4* A24 = (const float4*)A2;
        for (int i = tid; i < 128 * 16; i += 256) {
            int r = i >> 4, c4 = i & 15;
            int row = row0 + r;
            float4 v = make_float4(0.f, 0.f, 0.f, 0.f);
            if (row < NN) {
                v = A4[row * 16 + c4];
                if (!part) {
                    float4 w = A24[row * 16 + c4];
                    v.x += w.x; v.y += w.y; v.z += w.z; v.w += w.w;
                }
            }
            *(__half2*)&a_s[r][c4 * 4]     = __floats2half2_rn(v.x, v.y);
            *(__half2*)&a_s[r][c4 * 4 + 2] = __floats2half2_rn(v.z, v.w);
        }
    }
    __syncthreads();

    int wid = tid >> 5, lane = tid & 31;
    int wr0 = wid * 16;                       // warp's 16 rows within tile

    float acc[8][4];
#pragma unroll
    for (int n = 0; n < 8; n++)
#pragma unroll
        for (int j = 0; j < 4; j++) acc[n][j] = 0.f;

    unsigned a_base = (unsigned)__cvta_generic_to_shared(&a_s[0][0]);
    unsigned b_base = (unsigned)__cvta_generic_to_shared(&b_s[0][0]);
    // A ldmatrix.x4: lanes 0-15 -> rows wr0+lane @k0 ; lanes 16-31 -> same rows @k0+8
    unsigned aaddr = a_base + ((wr0 + (lane & 15)) * 72 + ((lane >> 4) * 8)) * 2;
    // B ldmatrix.x4.trans: lanes 0-15 -> rows k0+lane @n0 ; 16-31 -> @n0+8
    unsigned baddr = b_base + (((lane & 15)) * 72 + ((lane >> 4) * 8)) * 2;

#pragma unroll
    for (int ks = 0; ks < 4; ks++) {
        unsigned a0, a1, a2, a3;
        ldsm_x4(a0, a1, a2, a3, aaddr + (ks * 16 * 2));
#pragma unroll
        for (int g = 0; g < 4; g++) {
            unsigned b0, b1, b2, b3;
            ldsm_x4_t(b0, b1, b2, b3, baddr + ((ks * 16 * 72 + g * 16) * 2));
            mma16816(acc[2 * g],     a0, a1, a2, a3, b0, b1);
            mma16816(acc[2 * g + 1], a0, a1, a2, a3, b2, b3);
        }
    }

    // epilogue: *dinv, fp32 -> fp16, store (each 4-lane group writes 16B-contig)
    int r_lo = row0 + wr0 + (lane >> 2);
    int r_hi = r_lo + 8;
    int cq = lane & 3;
    float s_lo = (r_lo < NN) ? g_dinv[r_lo] : 0.f;
    float s_hi = (r_hi < NN) ? g_dinv[r_hi] : 0.f;
#pragma unroll
    for (int nt = 0; nt < 8; nt++) {
        if (r_lo < NN)
            out[r_lo * 32 + nt * 4 + cq] = __floats2half2_rn(acc[nt][0] * s_lo, acc[nt][1] * s_lo);
        if (r_hi < NN)
            out[r_hi * 32 + nt * 4 + cq] = __floats2half2_rn(acc[nt][2] * s_hi, acc[nt][3] * s_hi);
    }
}

// ---------------- dual sparse aggregation (warp per node) ------------------
__global__ void k_dualaggr(const __half2* __restrict__ tH, const float* __restrict__ bc,
                           float* __restrict__ h, int relu0,
                           const __half2* __restrict__ tP, const float* __restrict__ bp,
                           float* __restrict__ pe) {
    int gw = (blockIdx.x * blockDim.x + threadIdx.x) >> 5;
    int lane = threadIdx.x & 31;
    const __half2* t2;
    const float* bias;
    float* out;
    int relu, wid;
    if (gw < NN) {
        t2 = tH; bias = bc; out = h; relu = relu0; wid = gw;
    } else {
        wid = gw - NN;
        if (wid >= NN) return;
        t2 = tP; bias = bp; out = pe; relu = 1;
    }
    int beg = g_offs[wid], end = g_offs[wid + 1];
    float2 acc = __half22float2(t2[wid * 32 + lane]);  // self term (already *dinv)
    int e = beg;
    for (; e + 4 <= end; e += 4) {
        int s0 = g_csr[e], s1 = g_csr[e + 1], s2 = g_csr[e + 2], s3 = g_csr[e + 3];
        float2 v0 = __half22float2(t2[s0 * 32 + lane]);
        float2 v1 = __half22float2(t2[s1 * 32 + lane]);
        float2 v2 = __half22float2(t2[s2 * 32 + lane]);
        float2 v3 = __half22float2(t2[s3 * 32 + lane]);
        acc.x += (v0.x + v1.x) + (v2.x + v3.x);
        acc.y += (v0.y + v1.y) + (v2.y + v3.y);
    }
    for (; e < end; e++) {
        int s = g_csr[e];
        float2 v = __half22float2(t2[s * 32 + lane]);
        acc.x += v.x; acc.y += v.y;
    }
    float d = g_dinv[wid];
    float2 bv = ((const float2*)bias)[lane];
    float ox = acc.x * d + bv.x;
    float oy = acc.y * d + bv.y;
    if (relu) { ox = fmaxf(ox, 0.f); oy = fmaxf(oy, 0.f); }
    ((float2*)out)[wid * 32 + lane] = make_float2(ox, oy);
}

// ---------------- BatchNorm stats + fused norm/relu/pool -------------------
__global__ void k_bn_stats(const float* __restrict__ h) {
    int t = threadIdx.x;
    int col = t & 63, sub = t >> 6;
    float s = 0.f, s2 = 0.f;
    for (int r = blockIdx.x * 4 + sub; r < NN; r += gridDim.x * 4) {
        float v = h[r * 64 + col];
        s += v; s2 += v * v;
    }
    __shared__ float sh[4][64], sh2[4][64];
    sh[sub][col] = s; sh2[sub][col] = s2;
    __syncthreads();
    if (sub == 0) {
        float ts = sh[0][col] + sh[1][col] + sh[2][col] + sh[3][col];
        float t2 = sh2[0][col] + sh2[1][col] + sh2[2][col] + sh2[3][col];
        atomicAdd(&g_bnsum[col], ts);
        atomicAdd(&g_bnsum2[col], t2);
    }
}

__global__ void k_pool(const float* __restrict__ h, const int* __restrict__ ptr,
                       const float* __restrict__ gamma, const float* __restrict__ beta,
                       float* __restrict__ out) {
    __shared__ float sscale[64], sshift[64];
    int t = threadIdx.x;
    if (t < 64) {
        float mu = g_bnsum[t] / (float)NN;
        float var = g_bnsum2[t] / (float)NN - mu * mu;
        float r = rsqrtf(var + 1e-5f);
        float sc = r * gamma[t];
        sscale[t] = sc;
        sshift[t] = beta[t] - mu * sc;
    }
    __syncthreads();
    int g = blockIdx.x;
    int beg = ptr[g], end = ptr[g + 1];
    int col = t & 63, sub = t >> 6;
    float acc = 0.f;
    for (int r = beg + sub; r < end; r += 4) {
        float v = h[r * 64 + col] * sscale[col] + sshift[col];
        acc += fmaxf(v, 0.f);
    }
    __shared__ float sh[4][64];
    sh[sub][col] = acc;
    __syncthreads();
    if (sub == 0) {
        float s = sh[0][col] + sh[1][col] + sh[2][col] + sh[3][col];
        out[g * 64 + col] = s / (float)(end - beg);
    }
}

// ---------------- launch ----------------------------------------------------
extern "C" void kernel_launch(void* const* d_in, const int* in_sizes, int n_in,
                              void* d_out, int out_size) {
    const float* x     = (const float*)d_in[0];
    const float* rwpe  = (const float*)d_in[1];
    const float* W_rw  = (const float*)d_in[2];
    const float* b_rw  = (const float*)d_in[3];
    const float *Wc[5], *bc[5], *Wp[5], *bp[5];
    for (int i = 0; i < 5; i++) {
        Wc[i] = (const float*)d_in[4 + 4 * i];
        bc[i] = (const float*)d_in[5 + 4 * i];
        Wp[i] = (const float*)d_in[6 + 4 * i];
        bp[i] = (const float*)d_in[7 + 4 * i];
    }
    const float* gamma = (const float*)d_in[24];
    const float* beta  = (const float*)d_in[25];
    const int*   ei    = (const int*)d_in[26];
    const int*   ptr   = (const int*)d_in[27];
    float*       out   = (float*)d_out;
    const int* src = ei;
    const int* dst = ei + EE;

    float *pe, *h;
    __half2 *tH, *tP;
    cudaGetSymbolAddress((void**)&pe, g_pe);
    cudaGetSymbolAddress((void**)&h, g_h);
    cudaGetSymbolAddress((void**)&tH, g_tmpH);
    cudaGetSymbolAddress((void**)&tP, g_tmpP);

    // CSR build
    k_zero<<<(NN + 255) / 256, 256>>>();
    k_deg<<<(EE + 255) / 256, 256>>>(dst);
    k_scan_part<<<49, 1024>>>();
    k_scan_final<<<49, 1024>>>();
    k_scatter<<<(EE + 255) / 256, 256>>>(src, dst);

    // pe0 = RWPE @ W_rw + b_rw
    k_gemm_rw<<<(NN + 63) / 64, 256>>>(rwpe, W_rw, b_rw, pe);

    // layer 1
    k_dualgemm<<<2 * NB, 256>>>(x, pe, Wc[0], tH, pe, Wp[0], tP);
    k_dualaggr<<<2 * AGB, 256>>>(tH, bc[0], h, 1, tP, bp[0], pe);

    // layers 2..4: dual; layer 5: h-branch only, no relu
    for (int k = 1; k <= 3; k++) {
        k_dualgemm<<<2 * NB, 256>>>(h, pe, Wc[k], tH, pe, Wp[k], tP);
        k_dualaggr<<<2 * AGB, 256>>>(tH, bc[k], h, 1, tP, bp[k], pe);
    }
    k_dualgemm<<<NB, 256>>>(h, pe, Wc[4], tH, pe, Wp[4], tP);   // part0 only
    k_dualaggr<<<AGB, 256>>>(tH, bc[4], h, 0, tP, bp[4], pe);   // part0 only, no relu

    // BatchNorm (training stats) + relu + mean-pool per graph
    k_bn_stats<<<128, 256>>>(h);
    k_pool<<<GG, 256>>>(h, ptr, gamma, beta, out);
}